// round 5
// baseline (speedup 1.0000x reference)
#include <cuda_runtime.h>
#include <cstdint>

// Problem constants
#define B_    2
#define S_    2048
#define HID_  4096
#define NH_   32
#define NKV_  8
#define D_    128

// ---------------- scratch (__device__ globals; allocation-free) -------------
__device__ float g_Q[(size_t)B_ * S_ * NH_ * D_];    // [B,S,NH,D] (pre-rope)
__device__ float g_K[(size_t)B_ * S_ * NKV_ * D_];   // roped in-place
__device__ float g_V[(size_t)B_ * S_ * NKV_ * D_];
__device__ float g_A[(size_t)B_ * S_ * NH_ * D_];    // attn out (tf32-rounded)
__device__ float g_Wqt[(size_t)(NH_ * D_) * HID_];   // [N,K] transposed+rounded
__device__ float g_Wkt[(size_t)(NKV_ * D_) * HID_];
__device__ float g_Wvt[(size_t)(NKV_ * D_) * HID_];
__device__ float g_Wot[(size_t)HID_ * (NH_ * D_)];

__device__ __forceinline__ float tf32rn(float x) {
    uint32_t u;
    asm("cvt.rn.tf32.f32 %0, %1;" : "=r"(u) : "f"(x));
    return __uint_as_float(u);
}

// ---------------- pre-pass: W[K,N] -> Wt[N,K], tf32-rounded ------------------
__global__ void transpose_round_kernel(const float* __restrict__ W, float* __restrict__ Wt,
                                       int K, int N) {
    __shared__ float t[32][33];
    const int n0 = blockIdx.x * 32, k0 = blockIdx.y * 32;
    const int tx = threadIdx.x, ty = threadIdx.y;
#pragma unroll
    for (int j = 0; j < 32; j += 8)
        t[ty + j][tx] = W[(size_t)(k0 + ty + j) * N + n0 + tx];
    __syncthreads();
#pragma unroll
    for (int j = 0; j < 32; j += 8)
        Wt[(size_t)(n0 + ty + j) * K + k0 + tx] = tf32rn(t[tx][ty + j]);
}

// ---------------- mma helper -------------------------------------------------
__device__ __forceinline__ void mma_tf32(float* c, const uint32_t* a, const uint32_t* b) {
    asm volatile(
        "mma.sync.aligned.m16n8k8.row.col.f32.tf32.tf32.f32 "
        "{%0,%1,%2,%3}, {%4,%5,%6,%7}, {%8,%9}, {%0,%1,%2,%3};"
        : "+f"(c[0]), "+f"(c[1]), "+f"(c[2]), "+f"(c[3])
        : "r"(a[0]), "r"(a[1]), "r"(a[2]), "r"(a[3]), "r"(b[0]), "r"(b[1]));
}

// ---------------- tf32 mma.sync GEMM: C[M,N] = A[M,K] @ Bt[N,K]^T ------------
#define BM 128
#define BN 128
#define BK 32
#define TSTR 36
#define TILE_FLOATS (128 * TSTR)
#define GSM_BYTES (4 * TILE_FLOATS * 4)

__device__ __forceinline__ void g2s_tile(const float* __restrict__ G, float* sm,
                                         int row0, int K, int k0, int tid) {
#pragma unroll
    for (int i = 0; i < 4; i++) {
        int lin = tid + i * 256;
        int r = lin >> 3, c = lin & 7;
        float4 v = *(const float4*)(G + (size_t)(row0 + r) * K + k0 + c * 4);
        v.x = tf32rn(v.x); v.y = tf32rn(v.y); v.z = tf32rn(v.z); v.w = tf32rn(v.w);
        *(float4*)(sm + r * TSTR + c * 4) = v;
    }
}

__global__ __launch_bounds__(256) void tc_gemm(const float* __restrict__ A,
                                               const float* __restrict__ Bt,
                                               float* __restrict__ C,
                                               int M, int N, int K) {
    extern __shared__ float sm[];
    float* As[2] = {sm, sm + 2 * TILE_FLOATS};
    float* Bs[2] = {sm + TILE_FLOATS, sm + 3 * TILE_FLOATS};

    const int tid = threadIdx.x;
    const int lane = tid & 31, wid = tid >> 5;
    const int warpM = wid & 3;
    const int warpN = wid >> 2;
    const int ty8 = lane >> 2;
    const int tx4 = lane & 3;
    const int bm = blockIdx.y * BM, bn = blockIdx.x * BN;

    float acc[2][8][4];
#pragma unroll
    for (int mi = 0; mi < 2; mi++)
#pragma unroll
        for (int ni = 0; ni < 8; ni++)
#pragma unroll
            for (int r = 0; r < 4; r++) acc[mi][ni][r] = 0.f;

    g2s_tile(A, As[0], bm, K, 0, tid);
    g2s_tile(Bt, Bs[0], bn, K, 0, tid);
    __syncthreads();

    const int NK = K / BK;
    for (int kt = 0; kt < NK; kt++) {
        const int buf = kt & 1;
        if (kt + 1 < NK) {
            g2s_tile(A, As[buf ^ 1], bm, K, (kt + 1) * BK, tid);
            g2s_tile(Bt, Bs[buf ^ 1], bn, K, (kt + 1) * BK, tid);
        }
        const float* Ab = As[buf];
        const float* Bb = Bs[buf];
#pragma unroll
        for (int ks = 0; ks < 4; ks++) {
            const int k8 = ks * 8;
            uint32_t af[2][4];
#pragma unroll
            for (int mi = 0; mi < 2; mi++) {
                const int rb = warpM * 32 + mi * 16 + ty8;
                af[mi][0] = __float_as_uint(Ab[(rb) * TSTR + k8 + tx4]);
                af[mi][1] = __float_as_uint(Ab[(rb + 8) * TSTR + k8 + tx4]);
                af[mi][2] = __float_as_uint(Ab[(rb) * TSTR + k8 + 4 + tx4]);
                af[mi][3] = __float_as_uint(Ab[(rb + 8) * TSTR + k8 + 4 + tx4]);
            }
            uint32_t bf[8][2];
#pragma unroll
            for (int ni = 0; ni < 8; ni++) {
                const int nc = warpN * 64 + ni * 8 + ty8;
                bf[ni][0] = __float_as_uint(Bb[nc * TSTR + k8 + tx4]);
                bf[ni][1] = __float_as_uint(Bb[nc * TSTR + k8 + 4 + tx4]);
            }
#pragma unroll
            for (int mi = 0; mi < 2; mi++)
#pragma unroll
                for (int ni = 0; ni < 8; ni++)
                    mma_tf32(acc[mi][ni], af[mi], bf[ni]);
        }
        __syncthreads();
    }

#pragma unroll
    for (int mi = 0; mi < 2; mi++) {
        const int r0 = bm + warpM * 32 + mi * 16 + ty8;
#pragma unroll
        for (int ni = 0; ni < 8; ni++) {
            const int cc = bn + warpN * 64 + ni * 8 + 2 * tx4;
            *(float2*)(C + (size_t)r0 * N + cc)       = make_float2(acc[mi][ni][0], acc[mi][ni][1]);
            *(float2*)(C + (size_t)(r0 + 8) * N + cc) = make_float2(acc[mi][ni][2], acc[mi][ni][3]);
        }
    }
}

// ---------------- K RoPE (in-place, float4, 256-thread blocks) ---------------
__global__ __launch_bounds__(256) void rope_k_kernel(float* __restrict__ K,
                                                     const float* __restrict__ cosc,
                                                     const float* __restrict__ sinc) {
    const int idx = blockIdx.x * 256 + threadIdx.x;   // over rows*16 pair-float4
    const int r = idx >> 4;
    const int c4 = (idx & 15) << 2;                   // 0..60
    const int s = (r / NKV_) % S_;
    float* row = K + (size_t)r * D_;
    float4 x1 = *(float4*)(row + c4);
    float4 x2 = *(float4*)(row + c4 + 64);
    float4 c0 = *(const float4*)(cosc + s * D_ + c4);
    float4 s0 = *(const float4*)(sinc + s * D_ + c4);
    float4 c1 = *(const float4*)(cosc + s * D_ + c4 + 64);
    float4 s1 = *(const float4*)(sinc + s * D_ + c4 + 64);
    float4 o1, o2;
    o1.x = x1.x * c0.x - x2.x * s0.x;  o2.x = x2.x * c1.x + x1.x * s1.x;
    o1.y = x1.y * c0.y - x2.y * s0.y;  o2.y = x2.y * c1.y + x1.y * s1.y;
    o1.z = x1.z * c0.z - x2.z * s0.z;  o2.z = x2.z * c1.z + x1.z * s1.z;
    o1.w = x1.w * c0.w - x2.w * s0.w;  o2.w = x2.w * c1.w + x1.w * s1.w;
    *(float4*)(row + c4) = o1;
    *(float4*)(row + c4 + 64) = o2;
}

// ---------------- mma flash attention, 512 threads, split-KV column halves ---
// Q tile 128 rows, K tile 64 cols. 16 warps = 8 row-slabs x 2 kv-col-halves.
// QK = Qr*Khi + Qr*Klo (tf32, K hi/lo split). Per-warp partial softmax + O,
// pairwise merged at the end (split-softmax identity).
#define FQR 0
#define FKH (FQR + 128 * 132)       // 16896
#define FKL (FKH + 64 * 132)        // 25344
#define FVS (FKL + 64 * 132)        // 33792
#define FPS (FVS + 64 * 132)        // 42240
#define FL_FLOATS (FPS + 128 * 68)  // 50944
#define FL_SMEM_BYTES (FL_FLOATS * 4)

__global__ __launch_bounds__(512) void flash_mma_kernel(
    const float* __restrict__ Qg, const float* __restrict__ Kg,
    const float* __restrict__ Vg, const float* __restrict__ cosc,
    const float* __restrict__ sinc, float* __restrict__ Og) {
    extern __shared__ float sm[];
    float* Qr = sm + FQR;
    float* Kh = sm + FKH;
    float* Kl = sm + FKL;
    float* Vs = sm + FVS;
    float* Ps = sm + FPS;

    const int tid = threadIdx.x;
    const int lane = tid & 31, wid = tid >> 5;
    const int ty8 = lane >> 2;
    const int tx4 = lane & 3;
    const int qt = blockIdx.x;
    const int h  = blockIdx.y;
    const int b  = blockIdx.z;
    const int kvh = h >> 2;
    const int qbase = qt * 128;
    const int wrow = (wid >> 1) * 16;
    const int wcol = wid & 1;          // kv column half
    const float scale = 0.08838834764831845f;

    // ---- stage Q: RoPE + scale + tf32 round ----
#pragma unroll
    for (int i = 0; i < 4; i++) {
        int lin = i * 512 + tid;       // 2048 = 128 rows * 16 pair-positions
        int r = lin >> 4;
        int c4 = (lin & 15) << 2;      // 0..60
        const int sg = qbase + r;
        const float* qrow = Qg + ((size_t)((b * S_ + sg) * NH_ + h)) * D_;
        float4 x1 = *(const float4*)(qrow + c4);
        float4 x2 = *(const float4*)(qrow + c4 + 64);
        float4 c0 = *(const float4*)(cosc + sg * D_ + c4);
        float4 s0 = *(const float4*)(sinc + sg * D_ + c4);
        float4 c1 = *(const float4*)(cosc + sg * D_ + c4 + 64);
        float4 s1 = *(const float4*)(sinc + sg * D_ + c4 + 64);
        float o1[4], o2[4];
        o1[0] = x1.x * c0.x - x2.x * s0.x;  o2[0] = x2.x * c1.x + x1.x * s1.x;
        o1[1] = x1.y * c0.y - x2.y * s0.y;  o2[1] = x2.y * c1.y + x1.y * s1.y;
        o1[2] = x1.z * c0.z - x2.z * s0.z;  o2[2] = x2.z * c1.z + x1.z * s1.z;
        o1[3] = x1.w * c0.w - x2.w * s0.w;  o2[3] = x2.w * c1.w + x1.w * s1.w;
#pragma unroll
        for (int j = 0; j < 4; j++) {
            Qr[r * 132 + c4 + j]      = tf32rn(o1[j] * scale);
            Qr[r * 132 + c4 + 64 + j] = tf32rn(o2[j] * scale);
        }
    }
    __syncthreads();

    float m_i[2] = {-1e20f, -1e20f};
    float l_i[2] = {0.f, 0.f};
    float oacc[16][4];
#pragma unroll
    for (int ni = 0; ni < 16; ni++)
#pragma unroll
        for (int r = 0; r < 4; r++) oacc[ni][r] = 0.f;

    const int NKT = 2 * qt + 2;
    for (int kt = 0; kt < NKT; kt++) {
        const int kbase = kt * 64;
        // ---- load K (hi/lo) and V (tf32): 64 rows x 32 float4 each ----
#pragma unroll
        for (int i = 0; i < 4; i++) {
            int lin = i * 512 + tid;
            int r = lin >> 5;
            int c4 = (lin & 31) << 2;
            size_t gofs = ((size_t)((b * S_ + kbase + r) * NKV_ + kvh)) * D_ + c4;
            float4 kv = *(const float4*)(Kg + gofs);
            float kk[4] = {kv.x, kv.y, kv.z, kv.w};
#pragma unroll
            for (int j = 0; j < 4; j++) {
                float hi = tf32rn(kk[j]);
                Kh[r * 132 + c4 + j] = hi;
                Kl[r * 132 + c4 + j] = tf32rn(kk[j] - hi);
            }
            float4 vv = *(const float4*)(Vg + gofs);
            Vs[r * 132 + c4 + 0] = tf32rn(vv.x);
            Vs[r * 132 + c4 + 1] = tf32rn(vv.y);
            Vs[r * 132 + c4 + 2] = tf32rn(vv.z);
            Vs[r * 132 + c4 + 3] = tf32rn(vv.w);
        }
        __syncthreads();

        // ---- QK^T: warp's 16 rows x 32 cols (its column half) ----
        float sc[4][4];
#pragma unroll
        for (int ni = 0; ni < 4; ni++)
#pragma unroll
            for (int r = 0; r < 4; r++) sc[ni][r] = 0.f;

#pragma unroll
        for (int ks = 0; ks < 16; ks++) {
            const int k8 = ks * 8;
            uint32_t af[4];
            af[0] = __float_as_uint(Qr[(wrow + ty8) * 132 + k8 + tx4]);
            af[1] = __float_as_uint(Qr[(wrow + ty8 + 8) * 132 + k8 + tx4]);
            af[2] = __float_as_uint(Qr[(wrow + ty8) * 132 + k8 + 4 + tx4]);
            af[3] = __float_as_uint(Qr[(wrow + ty8 + 8) * 132 + k8 + 4 + tx4]);
#pragma unroll
            for (int ni = 0; ni < 4; ni++) {
                const int n = wcol * 32 + ni * 8 + ty8;
                uint32_t bh[2], bl[2];
                bh[0] = __float_as_uint(Kh[n * 132 + k8 + tx4]);
                bh[1] = __float_as_uint(Kh[n * 132 + k8 + 4 + tx4]);
                bl[0] = __float_as_uint(Kl[n * 132 + k8 + tx4]);
                bl[1] = __float_as_uint(Kl[n * 132 + k8 + 4 + tx4]);
                mma_tf32(sc[ni], af, bh);
                mma_tf32(sc[ni], af, bl);
            }
        }

        // ---- causal mask (last two k-tiles only) ----
        if (kbase + 63 > qbase) {
#pragma unroll
            for (int ni = 0; ni < 4; ni++) {
#pragma unroll
                for (int r = 0; r < 4; r++) {
                    int row = qbase + wrow + ty8 + ((r >= 2) ? 8 : 0);
                    int col = kbase + wcol * 32 + ni * 8 + 2 * tx4 + (r & 1);
                    if (col > row) sc[ni][r] = -1e30f;
                }
            }
        }

        // ---- partial online softmax (per warp, over its 32 cols) ----
#pragma unroll
        for (int rh = 0; rh < 2; rh++) {
            const int i0 = rh * 2, i1 = rh * 2 + 1;
            float mloc = -1e30f;
#pragma unroll
            for (int ni = 0; ni < 4; ni++)
                mloc = fmaxf(mloc, fmaxf(sc[ni][i0], sc[ni][i1]));
            mloc = fmaxf(mloc, __shfl_xor_sync(0xffffffffu, mloc, 1));
            mloc = fmaxf(mloc, __shfl_xor_sync(0xffffffffu, mloc, 2));
            const float mnew = fmaxf(m_i[rh], mloc);   // m_i starts at -1e20: clamp built in
            const float fac = __expf(m_i[rh] - mnew);
            m_i[rh] = mnew;
            float rsum = 0.f;
#pragma unroll
            for (int ni = 0; ni < 4; ni++) {
                float p0 = __expf(sc[ni][i0] - mnew);
                float p1 = __expf(sc[ni][i1] - mnew);
                sc[ni][i0] = p0; sc[ni][i1] = p1;
                rsum += p0 + p1;
            }
            rsum += __shfl_xor_sync(0xffffffffu, rsum, 1);
            rsum += __shfl_xor_sync(0xffffffffu, rsum, 2);
            l_i[rh] = l_i[rh] * fac + rsum;
#pragma unroll
            for (int ni = 0; ni < 16; ni++) {
                oacc[ni][i0] *= fac;
                oacc[ni][i1] *= fac;
            }
        }

        // ---- P to smem (warp-private region) ----
#pragma unroll
        for (int ni = 0; ni < 4; ni++) {
            const int cc = wcol * 32 + ni * 8 + 2 * tx4;
            *(float2*)&Ps[(wrow + ty8) * 68 + cc] =
                make_float2(tf32rn(sc[ni][0]), tf32rn(sc[ni][1]));
            *(float2*)&Ps[(wrow + ty8 + 8) * 68 + cc] =
                make_float2(tf32rn(sc[ni][2]), tf32rn(sc[ni][3]));
        }
        __syncwarp();

        // ---- PV over this warp's 32 kv rows, all 128 d ----
#pragma unroll
        for (int ks = 0; ks < 4; ks++) {
            const int k8 = wcol * 32 + ks * 8;
            uint32_t af[4];
            af[0] = __float_as_uint(Ps[(wrow + ty8) * 68 + k8 + tx4]);
            af[1] = __float_as_uint(Ps[(wrow + ty8 + 8) * 68 + k8 + tx4]);
            af[2] = __float_as_uint(Ps[(wrow + ty8) * 68 + k8 + 4 + tx4]);
            af[3] = __float_as_uint(Ps[(wrow + ty8 + 8) * 68 + k8 + 4 + tx4]);
#pragma unroll
            for (int ni = 0; ni < 16; ni++) {
                const int n = ni * 8 + ty8;   // d column
                uint32_t bf[2];
                bf[0] = __float_as_uint(Vs[(k8 + tx4) * 132 + n]);
                bf[1] = __float_as_uint(Vs[(k8 + 4 + tx4) * 132 + n]);
                mma_tf32(oacc[ni], af, bf);
            }
        }
        __syncthreads();
    }

    // ---- merge column-half partials (split-softmax identity) ----
    float* OX = sm + FQR;          // reuse: 128 x 132
    float* ML = sm + FKH;          // reuse: 128 x 2
    if (wcol == 1) {
#pragma unroll
        for (int ni = 0; ni < 16; ni++) {
            const int cc = ni * 8 + 2 * tx4;
            *(float2*)&OX[(wrow + ty8) * 132 + cc] = make_float2(oacc[ni][0], oacc[ni][1]);
            *(float2*)&OX[(wrow + ty8 + 8) * 132 + cc] = make_float2(oacc[ni][2], oacc[ni][3]);
        }
        if (tx4 == 0) {
            ML[(wrow + ty8) * 2 + 0] = m_i[0];
            ML[(wrow + ty8) * 2 + 1] = l_i[0];
            ML[(wrow + ty8 + 8) * 2 + 0] = m_i[1];
            ML[(wrow + ty8 + 8) * 2 + 1] = l_i[1];
        }
    }
    __syncthreads();
    if (wcol == 0) {
        float fs[2], fp[2], inv[2];
#pragma unroll
        for (int rh = 0; rh < 2; rh++) {
            const int row = wrow + ty8 + rh * 8;
            const float mp = ML[row * 2 + 0];
            const float lp = ML[row * 2 + 1];
            const float mt = fmaxf(m_i[rh], mp);
            fs[rh] = __expf(m_i[rh] - mt);
            fp[rh] = __expf(mp - mt);
            inv[rh] = 1.0f / (fs[rh] * l_i[rh] + fp[rh] * lp);
        }
        const int r0 = qbase + wrow + ty8;
#pragma unroll
        for (int ni = 0; ni < 16; ni++) {
            const int cc = ni * 8 + 2 * tx4;
            const float* ox0 = &OX[(wrow + ty8) * 132 + cc];
            const float* ox1 = &OX[(wrow + ty8 + 8) * 132 + cc];
            float* p0 = Og + ((size_t)((b * S_ + r0) * NH_ + h)) * D_ + cc;
            float* p1 = Og + ((size_t)((b * S_ + r0 + 8) * NH_ + h)) * D_ + cc;
            *(float2*)p0 = make_float2(
                tf32rn((fs[0] * oacc[ni][0] + fp[0] * ox0[0]) * inv[0]),
                tf32rn((fs[0] * oacc[ni][1] + fp[0] * ox0[1]) * inv[0]));
            *(float2*)p1 = make_float2(
                tf32rn((fs[1] * oacc[ni][2] + fp[1] * ox1[0]) * inv[1]),
                tf32rn((fs[1] * oacc[ni][3] + fp[1] * ox1[1]) * inv[1]));
        }
    }
}

// ---------------- launch ----------------------------------------------------
extern "C" void kernel_launch(void* const* d_in, const int* in_sizes, int n_in,
                              void* d_out, int out_size) {
    const float* X    = (const float*)d_in[0];
    const float* Wq   = (const float*)d_in[1];
    const float* Wk   = (const float*)d_in[2];
    const float* Wv   = (const float*)d_in[3];
    const float* Wo   = (const float*)d_in[4];
    const float* cosc = (const float*)d_in[5];
    const float* sinc = (const float*)d_in[6];
    float* out = (float*)d_out;

    float *Qp, *Kp, *Vp, *Ap, *Wqt, *Wkt, *Wvt, *Wot;
    cudaGetSymbolAddress((void**)&Qp, g_Q);
    cudaGetSymbolAddress((void**)&Kp, g_K);
    cudaGetSymbolAddress((void**)&Vp, g_V);
    cudaGetSymbolAddress((void**)&Ap, g_A);
    cudaGetSymbolAddress((void**)&Wqt, g_Wqt);
    cudaGetSymbolAddress((void**)&Wkt, g_Wkt);
    cudaGetSymbolAddress((void**)&Wvt, g_Wvt);
    cudaGetSymbolAddress((void**)&Wot, g_Wot);

    const int M = B_ * S_;          // 4096
    const int NQ = NH_ * D_;        // 4096
    const int NKVD = NKV_ * D_;     // 1024

    // Pre-pass: transpose+round weights to [N,K]
    {
        dim3 blk(32, 8);
        transpose_round_kernel<<<dim3(NQ / 32, HID_ / 32), blk>>>(Wq, Wqt, HID_, NQ);
        transpose_round_kernel<<<dim3(NKVD / 32, HID_ / 32), blk>>>(Wk, Wkt, HID_, NKVD);
        transpose_round_kernel<<<dim3(NKVD / 32, HID_ / 32), blk>>>(Wv, Wvt, HID_, NKVD);
        transpose_round_kernel<<<dim3(HID_ / 32, NQ / 32), blk>>>(Wo, Wot, NQ, HID_);
    }

    cudaFuncSetAttribute(tc_gemm, cudaFuncAttributeMaxDynamicSharedMemorySize, GSM_BYTES);

    // Projections (mma.sync tf32; rounding fused into g2s)
    tc_gemm<<<dim3(NQ / BN, M / BM), 256, GSM_BYTES>>>(X, Wqt, Qp, M, NQ, HID_);
    tc_gemm<<<dim3(NKVD / BN, M / BM), 256, GSM_BYTES>>>(X, Wkt, Kp, M, NKVD, HID_);
    tc_gemm<<<dim3(NKVD / BN, M / BM), 256, GSM_BYTES>>>(X, Wvt, Vp, M, NKVD, HID_);

    // K RoPE in-place (Q RoPE fused into flash)
    rope_k_kernel<<<(M * NKV_ * 16) / 256, 256>>>(Kp, cosc, sinc);

    // Flash attention (512 threads, split-KV column halves)
    cudaFuncSetAttribute(flash_mma_kernel, cudaFuncAttributeMaxDynamicSharedMemorySize, FL_SMEM_BYTES);
    flash_mma_kernel<<<dim3(S_ / 128, NH_, B_), 512, FL_SMEM_BYTES>>>(Qp, Kp, Vp, cosc, sinc, Ap);

    // Output projection
    tc_gemm<<<dim3(HID_ / BN, M / BM), 256, GSM_BYTES>>>(Ap, Wot, out, M, HID_, NQ);
}